// round 16
// baseline (speedup 1.0000x reference)
#include <cuda_runtime.h>
#include <cuda_bf16.h>
#include <math.h>
#include <stdint.h>

// ---------------------------------------------------------------------------
// LightGlue forward. L=9, D=256, H=4, HD=64, N=1024, B=4 (2 pairs).
// tf32 mma dense GEMMs with fused RoPE-split / head-split epilogues.
// Flash attention: 64-key tiles, 89 KB smem, 2 CTAs/SM.
// Measured-best configuration (round 10: 2517 us).
// ---------------------------------------------------------------------------

#define LGB   4
#define LGN   1024
#define LGD   256
#define LGH   4
#define LGHD  64
#define LGL   9
#define M4    (LGB*LGN)
#define BH    (LGB*LGH)
#define NN2   (2*1024*1024)

// -------------------- scratch (device globals; no allocation) --------------
__device__ float g_x   [M4*LGD];
__device__ float g_Q   [BH*LGN*LGHD];
__device__ float g_K   [BH*LGN*LGHD];
__device__ float g_V   [BH*LGN*LGHD];
__device__ float g_ctx [M4*LGD];
__device__ float g_cat [M4*2*LGD];
__device__ float g_h1  [M4*2*LGD];
__device__ float g_h2  [M4*2*LGD];
__device__ float g_md  [M4*LGD];
__device__ float g_sim [NN2];
__device__ float g_z   [M4];
__device__ float g_lser[2*LGN];
__device__ float g_lsec[2*LGN];
__device__ int   g_m0  [LGN];
__device__ int   g_m1  [LGN];
__device__ float g_rmax[LGN];
__device__ float g_wr  [11283712];        // tf32-rounded weights + biases

// -------------------- tf32 helpers -----------------------------------------
__device__ __forceinline__ uint32_t tf32u(float x) {
    uint32_t u;
    asm("cvt.rna.tf32.f32 %0, %1;" : "=r"(u) : "f"(x));
    return u;
}
__device__ __forceinline__ float tf32r(float x) { return __uint_as_float(tf32u(x)); }

__device__ __forceinline__ void mma_tf32(float (&d)[4], const uint32_t (&a)[4],
                                         const uint32_t (&b)[2]) {
    asm volatile(
        "mma.sync.aligned.m16n8k8.row.col.f32.tf32.tf32.f32 "
        "{%0,%1,%2,%3}, {%4,%5,%6,%7}, {%8,%9}, {%0,%1,%2,%3};"
        : "+f"(d[0]), "+f"(d[1]), "+f"(d[2]), "+f"(d[3])
        : "r"(a[0]), "r"(a[1]), "r"(a[2]), "r"(a[3]), "r"(b[0]), "r"(b[1]));
}

__device__ __forceinline__ void cp16(void* dst, const void* src) {
    uint32_t d = (uint32_t)__cvta_generic_to_shared(dst);
    asm volatile("cp.async.cg.shared.global [%0], [%1], 16;" :: "r"(d), "l"(src));
}
__device__ __forceinline__ void cp_commit() { asm volatile("cp.async.commit_group;"); }
template<int n> __device__ __forceinline__ void cp_wait() {
    asm volatile("cp.async.wait_group %0;" :: "n"(n));
}

// -------------------- weight prep kernels -----------------------------------
__global__ void roundw4_k(const float4* __restrict__ src, float4* __restrict__ dst,
                          int n4) {
    int i = blockIdx.x * blockDim.x + threadIdx.x;
    if (i >= n4) return;
    float4 v = src[i];
    v.x = tf32r(v.x); v.y = tf32r(v.y); v.z = tf32r(v.z); v.w = tf32r(v.w);
    dst[i] = v;
}

// qkv weight permute+round: src rows interleaved (out = 3d+sec) -> [q|k|v]
__global__ void permqkv_k(const float4* __restrict__ src, float4* __restrict__ dst) {
    int i = blockIdx.x * blockDim.x + threadIdx.x;       // LGL*768*64
    if (i >= LGL * 768 * 64) return;
    int k4 = i & 63;
    int row = (i >> 6) % 768;
    int l = i / (768 * 64);
    int sec = row >> 8, d = row & 255;
    float4 v = src[((long)l * 768 + 3 * d + sec) * 64 + k4];
    v.x = tf32r(v.x); v.y = tf32r(v.y); v.z = tf32r(v.z); v.w = tf32r(v.w);
    dst[i] = v;
}
__global__ void permqkvb_k(const float* __restrict__ src, float* __restrict__ dst) {
    int i = blockIdx.x * blockDim.x + threadIdx.x;       // LGL*768
    if (i >= LGL * 768) return;
    int row = i % 768, l = i / 768;
    int sec = row >> 8, d = row & 255;
    dst[i] = src[l * 768 + 3 * d + sec];
}

// pack cQK / cV weights into [qk|v] per layer, rounded
__global__ void pack2_k(const float4* __restrict__ a, const float4* __restrict__ b,
                        float4* __restrict__ dst) {
    int i = blockIdx.x * blockDim.x + threadIdx.x;       // LGL*512*64
    if (i >= LGL * 512 * 64) return;
    int k4 = i & 63;
    int row = (i >> 6) % 512;
    int l = i / (512 * 64);
    int sec = row >> 8, r = row & 255;
    const float4* s = sec ? b : a;
    float4 v = s[((long)l * 256 + r) * 64 + k4];
    v.x = tf32r(v.x); v.y = tf32r(v.y); v.z = tf32r(v.z); v.w = tf32r(v.w);
    dst[i] = v;
}
__global__ void pack2b_k(const float* __restrict__ a, const float* __restrict__ b,
                         float* __restrict__ dst) {
    int i = blockIdx.x * blockDim.x + threadIdx.x;       // LGL*512
    if (i >= LGL * 512) return;
    int row = i % 512, l = i / 512;
    dst[i] = (row >= 256) ? b[l * 256 + row - 256] : a[l * 256 + row];
}

// -------------------- dense tf32 GEMM (NT only) -----------------------------
// B pre-rounded. A pre-rounded iff RNDA==0.
// EPI=0: normal epilogue (C, optional C2, rnd).  alpha/res supported.
// EPI=1: qkv+RoPE epilogue -> writes Qo/Ko/Vo split-head, tf32-rounded.
// EPI=2: packed qk|v epilogue -> writes Qo/Vo split-head, tf32-rounded.
#define GSTR 36

template<int BM, int RNDA, int EPI>
__global__ void __launch_bounds__(BM * 2, (BM == 128) ? 2 : 3) tgemm_k(
    const float* __restrict__ A, const float* __restrict__ B, float* C,
    int M, int N, int K, int ldC,
    long sA, long sB, long sC,
    const float* __restrict__ bias, const float* res, float alpha,
    float* C2, int rnd,
    float* Qo, float* Ko, float* Vo,
    const float* __restrict__ kpts, const float* __restrict__ Wr)
{
    constexpr int THREADS = BM * 2;
    constexpr int WCNT = (BM == 128) ? 4 : 2;
    constexpr int TM   = BM / 32;
    constexpr int TN   = 16 / WCNT;
    constexpr int ABUF = BM * GSTR;
    constexpr int BBUF = 128 * GSTR;

    extern __shared__ float sm[];
    float* As = sm;
    float* Bs = sm + 2 * ABUF;

    int bh = blockIdx.z;
    A += (long)bh * sA;
    B += (long)bh * sB;
    if (EPI == 0) {
        C += (long)bh * sC;
        if (res) res += (long)bh * sC;
    }

    const int tid  = threadIdx.x;
    const int warp = tid >> 5, lane = tid & 31;
    const int wm = warp / WCNT, wn = warp % WCNT;
    const int gid = lane >> 2, tig = lane & 3;
    const int row0 = blockIdx.y * BM;
    const int col0 = blockIdx.x * 128;

    float acc[TM][TN][4];
#pragma unroll
    for (int i = 0; i < TM; i++)
#pragma unroll
        for (int j = 0; j < TN; j++)
#pragma unroll
            for (int q = 0; q < 4; q++) acc[i][j][q] = 0.0f;

#define LOADT(s, k0) do {                                                      \
    _Pragma("unroll")                                                          \
    for (int l = 0; l < BM * 8 / THREADS; l++) {                               \
        int v = tid + THREADS * l; int r = v >> 3; int off = (v & 7) * 4;      \
        cp16(&As[(s) * ABUF + r * GSTR + off],                                 \
             &A[(long)(row0 + r) * K + (k0) + off]);                           \
    }                                                                          \
    _Pragma("unroll")                                                          \
    for (int l = 0; l < 1024 / THREADS; l++) {                                 \
        int v = tid + THREADS * l; int r = v >> 3; int off = (v & 7) * 4;      \
        cp16(&Bs[(s) * BBUF + r * GSTR + off],                                 \
             &B[(long)(col0 + r) * K + (k0) + off]);                           \
    }                                                                          \
    cp_commit(); } while (0)

    const int NK = K >> 5;
    LOADT(0, 0);

    for (int it = 0; it < NK; it++) {
        int cur = it & 1;
        cp_wait<0>();
        __syncthreads();
        if (it + 1 < NK) LOADT(cur ^ 1, (it + 1) << 5);
        const float* Ab = As + cur * ABUF;
        const float* Bb = Bs + cur * BBUF;

#pragma unroll
        for (int ks = 0; ks < 32; ks += 8) {
            uint32_t ar[TM][4];
#pragma unroll
            for (int tm = 0; tm < TM; tm++) {
                int mr = (wm * (TM * 16) + tm * 16 + gid) * GSTR;
                if (RNDA) {
                    ar[tm][0] = tf32u(Ab[mr + ks + tig]);
                    ar[tm][1] = tf32u(Ab[mr + 8 * GSTR + ks + tig]);
                    ar[tm][2] = tf32u(Ab[mr + ks + tig + 4]);
                    ar[tm][3] = tf32u(Ab[mr + 8 * GSTR + ks + tig + 4]);
                } else {
                    ar[tm][0] = __float_as_uint(Ab[mr + ks + tig]);
                    ar[tm][1] = __float_as_uint(Ab[mr + 8 * GSTR + ks + tig]);
                    ar[tm][2] = __float_as_uint(Ab[mr + ks + tig + 4]);
                    ar[tm][3] = __float_as_uint(Ab[mr + 8 * GSTR + ks + tig + 4]);
                }
            }
            uint32_t br[TN][2];
#pragma unroll
            for (int tn = 0; tn < TN; tn++) {
                int nr = (wn * (TN * 8) + tn * 8 + gid) * GSTR;
                br[tn][0] = __float_as_uint(Bb[nr + ks + tig]);
                br[tn][1] = __float_as_uint(Bb[nr + ks + tig + 4]);
            }
#pragma unroll
            for (int tm = 0; tm < TM; tm++)
#pragma unroll
                for (int tn = 0; tn < TN; tn++)
                    mma_tf32(acc[tm][tn], ar[tm], br[tn]);
        }
        __syncthreads();
    }
#undef LOADT

    if (EPI == 0) {
#pragma unroll
        for (int tm = 0; tm < TM; tm++) {
            int r0 = row0 + wm * (TM * 16) + tm * 16 + gid;
#pragma unroll
            for (int tn = 0; tn < TN; tn++) {
                int c = col0 + wn * (TN * 8) + tn * 8 + tig * 2;
                float b0 = bias ? bias[c] : 0.0f;
                float b1 = bias ? bias[c + 1] : 0.0f;
#pragma unroll
                for (int half = 0; half < 2; half++) {
                    int r = r0 + half * 8;
                    float v0 = (acc[tm][tn][half * 2 + 0] + b0) * alpha;
                    float v1 = (acc[tm][tn][half * 2 + 1] + b1) * alpha;
                    if (res) {
                        v0 += res[(long)r * ldC + c];
                        v1 += res[(long)r * ldC + c + 1];
                    }
                    float u0 = v0, u1 = v1;
                    if (rnd & 1) { v0 = tf32r(v0); v1 = tf32r(v1); }
                    *reinterpret_cast<float2*>(&C[(long)r * ldC + c]) = make_float2(v0, v1);
                    if (C2) {
                        if (rnd & 2) { u0 = tf32r(u0); u1 = tf32r(u1); }
                        else         { u0 = v0; u1 = v1; }
                        *reinterpret_cast<float2*>(&C2[(long)r * 512 + c]) = make_float2(u0, u1);
                    }
                }
            }
        }
    } else {
        // split-head (+RoPE for EPI=1) epilogue
#pragma unroll
        for (int tm = 0; tm < TM; tm++) {
            int r0 = row0 + wm * (TM * 16) + tm * 16 + gid;
#pragma unroll
            for (int tn = 0; tn < TN; tn++) {
                int c = col0 + wn * (TN * 8) + tn * 8 + tig * 2;
                int sec = c >> 8;
                int d = c & 255;
                int h = d >> 6, e = d & 63;
                float b0 = bias[c], b1 = bias[c + 1];
                float w0 = 0.0f, w1 = 0.0f;
                if (EPI == 1 && sec < 2) {
                    int f = e >> 1;
                    w0 = Wr[2 * f]; w1 = Wr[2 * f + 1];
                }
#pragma unroll
                for (int half = 0; half < 2; half++) {
                    int r = r0 + half * 8;
                    float v0 = acc[tm][tn][half * 2 + 0] + b0;
                    float v1 = acc[tm][tn][half * 2 + 1] + b1;
                    int b_ = r >> 10, n = r & (LGN - 1);
                    long base = (((long)(b_ * LGH + h)) * LGN + n) * LGHD + e;
                    if (EPI == 1) {
                        if (sec < 2) {
                            float kx = kpts[r * 2], ky = kpts[r * 2 + 1];
                            float pr = kx * w0 + ky * w1;
                            float co = cosf(pr), si = sinf(pr);
                            float* dst = (sec == 0) ? Qo : Ko;
                            dst[base]     = tf32r(co * v0 - si * v1);
                            dst[base + 1] = tf32r(co * v1 + si * v0);
                        } else {
                            Vo[base]     = tf32r(v0);
                            Vo[base + 1] = tf32r(v1);
                        }
                    } else {
                        float* dst = (sec == 0) ? Qo : Vo;
                        dst[base]     = tf32r(v0);
                        dst[base + 1] = tf32r(v1);
                    }
                }
            }
        }
    }
}

// -------------------- fused flash attention ---------------------------------
// Q,K,V pre-rounded tf32, [16 heads][1024][64]. ctx out merged, rounded.
// 64-query CTAs (4 warps x 16 rows), 64-key tiles, 89 KB smem, 2 CTAs/SM.
#define FKS 68
#define FVS 72
#define FKBUF (64*FKS)
#define FVBUF (64*FVS)
#define FSMEM ((2*FKBUF + 2*FVBUF + 64*FKS) * 4)   // 89088 bytes

__global__ void __launch_bounds__(128, 2) flash_k(
    const float* __restrict__ Qg, const float* __restrict__ Kg,
    const float* __restrict__ Vg, float* __restrict__ ctx, int xorB)
{
    extern __shared__ float smf[];
    float* Ksm = smf;                         // [2][64][68]
    float* Vsm = smf + 2 * FKBUF;             // [2][64][72]
    float* Ps  = smf + 2 * FKBUF + 2 * FVBUF; // [64][68]

    const int bh = blockIdx.y, qt = blockIdx.x;
    const float* Qh = Qg + (long)bh * (LGN * LGHD);
    const float* Kh = Kg + (long)(bh ^ xorB) * (LGN * LGHD);
    const float* Vh = Vg + (long)(bh ^ xorB) * (LGN * LGHD);

    const int tid = threadIdx.x, warp = tid >> 5, lane = tid & 31;
    const int gid = lane >> 2, tig = lane & 3;
    const int wrow = warp * 16;

#pragma unroll
    for (int l = 0; l < 8; l++) {
        int v = tid + 128 * l;
        int r = v >> 4, c = (v & 15) * 4;
        float4 q = *(const float4*)&Qh[(long)(qt * 64 + r) * LGHD + c];
        Ps[r * FKS + c]     = 0.125f * q.x; Ps[r * FKS + c + 1] = 0.125f * q.y;
        Ps[r * FKS + c + 2] = 0.125f * q.z; Ps[r * FKS + c + 3] = 0.125f * q.w;
    }
    __syncthreads();
    uint32_t qa[8][4];
#pragma unroll
    for (int ks = 0; ks < 8; ks++) {
        int k = ks * 8;
        qa[ks][0] = __float_as_uint(Ps[(wrow + gid) * FKS + k + tig]);
        qa[ks][1] = __float_as_uint(Ps[(wrow + gid + 8) * FKS + k + tig]);
        qa[ks][2] = __float_as_uint(Ps[(wrow + gid) * FKS + k + tig + 4]);
        qa[ks][3] = __float_as_uint(Ps[(wrow + gid + 8) * FKS + k + tig + 4]);
    }

    float oacc[8][4];
#pragma unroll
    for (int nt = 0; nt < 8; nt++)
#pragma unroll
        for (int j = 0; j < 4; j++) oacc[nt][j] = 0.0f;
    float mrow0 = -INFINITY, mrow1 = -INFINITY, lrow0 = 0.0f, lrow1 = 0.0f;

#define LOADKV(s, kt) do {                                                     \
    _Pragma("unroll")                                                          \
    for (int l = 0; l < 8; l++) {                                              \
        int v = tid + 128 * l; int r = v >> 4; int c = (v & 15) * 4;           \
        cp16(&Ksm[(s) * FKBUF + r * FKS + c],                                  \
             &Kh[(long)((kt) * 64 + r) * LGHD + c]);                           \
    }                                                                          \
    _Pragma("unroll")                                                          \
    for (int l = 0; l < 8; l++) {                                              \
        int v = tid + 128 * l; int r = v >> 4; int c = (v & 15) * 4;           \
        cp16(&Vsm[(s) * FVBUF + r * FVS + c],                                  \
             &Vh[(long)((kt) * 64 + r) * LGHD + c]);                           \
    }                                                                          \
    cp_commit(); } while (0)

    LOADKV(0, 0);

    for (int kt = 0; kt < 16; kt++) {
        int cur = kt & 1;
        cp_wait<0>();
        __syncthreads();
        if (kt + 1 < 16) LOADKV(cur ^ 1, kt + 1);
        const float* K_ = Ksm + cur * FKBUF;
        const float* V_ = Vsm + cur * FVBUF;

        float sacc[8][4];
#pragma unroll
        for (int nt = 0; nt < 8; nt++)
#pragma unroll
            for (int j = 0; j < 4; j++) sacc[nt][j] = 0.0f;
#pragma unroll
        for (int ks = 0; ks < 8; ks++) {
            int k = ks * 8;
#pragma unroll
            for (int nt = 0; nt < 8; nt++) {
                uint32_t b[2];
                b[0] = __float_as_uint(K_[(nt * 8 + gid) * FKS + k + tig]);
                b[1] = __float_as_uint(K_[(nt * 8 + gid) * FKS + k + tig + 4]);
                mma_tf32(sacc[nt], qa[ks], b);
            }
        }

        float t0 = -INFINITY, t1 = -INFINITY;
#pragma unroll
        for (int nt = 0; nt < 8; nt++) {
            t0 = fmaxf(t0, fmaxf(sacc[nt][0], sacc[nt][1]));
            t1 = fmaxf(t1, fmaxf(sacc[nt][2], sacc[nt][3]));
        }
        t0 = fmaxf(t0, __shfl_xor_sync(0xffffffffu, t0, 1));
        t0 = fmaxf(t0, __shfl_xor_sync(0xffffffffu, t0, 2));
        t1 = fmaxf(t1, __shfl_xor_sync(0xffffffffu, t1, 1));
        t1 = fmaxf(t1, __shfl_xor_sync(0xffffffffu, t1, 2));
        float mn0 = fmaxf(mrow0, t0), mn1 = fmaxf(mrow1, t1);
        float al0 = __expf(mrow0 - mn0), al1 = __expf(mrow1 - mn1);
        float s0 = 0.0f, s1 = 0.0f;
#pragma unroll
        for (int nt = 0; nt < 8; nt++) {
            sacc[nt][0] = __expf(sacc[nt][0] - mn0);
            sacc[nt][1] = __expf(sacc[nt][1] - mn0);
            sacc[nt][2] = __expf(sacc[nt][2] - mn1);
            sacc[nt][3] = __expf(sacc[nt][3] - mn1);
            s0 += sacc[nt][0] + sacc[nt][1];
            s1 += sacc[nt][2] + sacc[nt][3];
        }
        s0 += __shfl_xor_sync(0xffffffffu, s0, 1);
        s0 += __shfl_xor_sync(0xffffffffu, s0, 2);
        s1 += __shfl_xor_sync(0xffffffffu, s1, 1);
        s1 += __shfl_xor_sync(0xffffffffu, s1, 2);
        lrow0 = lrow0 * al0 + s0;
        lrow1 = lrow1 * al1 + s1;
        mrow0 = mn0; mrow1 = mn1;

#pragma unroll
        for (int nt = 0; nt < 8; nt++) {
            oacc[nt][0] *= al0; oacc[nt][1] *= al0;
            oacc[nt][2] *= al1; oacc[nt][3] *= al1;
            int c = nt * 8 + 2 * tig;
            Ps[(wrow + gid) * FKS + c]         = __uint_as_float(tf32u(sacc[nt][0]));
            Ps[(wrow + gid) * FKS + c + 1]     = __uint_as_float(tf32u(sacc[nt][1]));
            Ps[(wrow + gid + 8) * FKS + c]     = __uint_as_float(tf32u(sacc[nt][2]));
            Ps[(wrow + gid + 8) * FKS + c + 1] = __uint_as_float(tf32u(sacc[nt][3]));
        }
        __syncwarp();

#pragma unroll
        for (int ks = 0; ks < 8; ks++) {
            int k = ks * 8;
            uint32_t pa[4];
            pa[0] = __float_as_uint(Ps[(wrow + gid) * FKS + k + tig]);
            pa[1] = __float_as_uint(Ps[(wrow + gid + 8) * FKS + k + tig]);
            pa[2] = __float_as_uint(Ps[(wrow + gid) * FKS + k + tig + 4]);
            pa[3] = __float_as_uint(Ps[(wrow + gid + 8) * FKS + k + tig + 4]);
#pragma unroll
            for (int nt = 0; nt < 8; nt++) {
                uint32_t b[2];
                b[0] = __float_as_uint(V_[(k + tig) * FVS + nt * 8 + gid]);
                b[1] = __float_as_uint(V_[(k + tig + 4) * FVS + nt * 8 + gid]);
                mma_tf32(oacc[nt], pa, b);
            }
        }
        __syncthreads();
    }
#undef LOADKV

    float inv0 = 1.0f / lrow0, inv1 = 1.0f / lrow1;
    int b_ = bh >> 2, h = bh & 3;
    int n0 = qt * 64 + wrow + gid;
    long base0 = ((long)(b_ * LGN + n0)) * LGD + h * 64;
    long base1 = base0 + 8L * LGD;
#pragma unroll
    for (int nt = 0; nt < 8; nt++) {
        int c = nt * 8 + 2 * tig;
        *(float2*)&ctx[base0 + c] =
            make_float2(tf32r(oacc[nt][0] * inv0), tf32r(oacc[nt][1] * inv0));
        *(float2*)&ctx[base1 + c] =
            make_float2(tf32r(oacc[nt][2] * inv1), tf32r(oacc[nt][3] * inv1));
    }
}

// -------------------- elementwise / reduction kernels ----------------------
__global__ void copy2_k(const float* __restrict__ src, float* __restrict__ x,
                        float* __restrict__ cat) {
    int i = blockIdx.x * blockDim.x + threadIdx.x;
    if (i >= M4 * LGD) return;
    float v = src[i];
    x[i] = v;
    int r = i >> 8, c = i & 255;
    cat[(long)r * 512 + c] = tf32r(v);
}

// LayerNorm(512) + exact GELU; warp-shuffle reduction; output tf32-rounded.
__global__ void lngelu_k(const float* __restrict__ h, const float* __restrict__ g,
                         const float* __restrict__ bb, float* __restrict__ o)
{
    long row = blockIdx.x;
    int tid = threadIdx.x;
    int lane = tid & 31, warp = tid >> 5;
    const float* p = h + row * 512;
    float x0 = p[tid], x1 = p[tid + 256];
    float s1 = x0 + x1, s2 = x0 * x0 + x1 * x1;
#pragma unroll
    for (int off = 16; off > 0; off >>= 1) {
        s1 += __shfl_xor_sync(0xffffffffu, s1, off);
        s2 += __shfl_xor_sync(0xffffffffu, s2, off);
    }
    __shared__ float sm1[8], sm2[8];
    if (lane == 0) { sm1[warp] = s1; sm2[warp] = s2; }
    __syncthreads();
    float t1 = 0.0f, t2 = 0.0f;
#pragma unroll
    for (int w = 0; w < 8; w++) { t1 += sm1[w]; t2 += sm2[w]; }
    float mean = t1 * (1.0f / 512.0f);
    float var  = t2 * (1.0f / 512.0f) - mean * mean;
    float rr = rsqrtf(var + 1e-5f);
    float n0 = (x0 - mean) * rr * g[tid] + bb[tid];
    float n1 = (x1 - mean) * rr * g[tid + 256] + bb[tid + 256];
    o[row * 512 + tid]       = tf32r(0.5f * n0 * (1.0f + erff(n0 * 0.70710678118654752f)));
    o[row * 512 + tid + 256] = tf32r(0.5f * n1 * (1.0f + erff(n1 * 0.70710678118654752f)));
}

__global__ void z_k(const float* __restrict__ x, const float* __restrict__ w,
                    const float* __restrict__ b, float* __restrict__ z)
{
    long row = blockIdx.x;
    int tid = threadIdx.x;
    __shared__ float red[256];
    red[tid] = x[row * LGD + tid] * w[tid];
    __syncthreads();
    for (int s = 128; s > 0; s >>= 1) { if (tid < s) red[tid] += red[tid + s]; __syncthreads(); }
    if (tid == 0) z[row] = red[0] + b[0];
}

__global__ void lse_row_k(const float* __restrict__ sim, float* __restrict__ lser)
{
    long r = blockIdx.x;
    const float* p = sim + r * LGN;
    int tid = threadIdx.x;
    __shared__ float red[256];
    float m = -INFINITY;
    for (int j = tid; j < LGN; j += 256) m = fmaxf(m, p[j]);
    red[tid] = m; __syncthreads();
    for (int s = 128; s > 0; s >>= 1) { if (tid < s) red[tid] = fmaxf(red[tid], red[tid + s]); __syncthreads(); }
    m = red[0];
    __syncthreads();
    float sum = 0.0f;
    for (int j = tid; j < LGN; j += 256) sum += expf(p[j] - m);
    red[tid] = sum; __syncthreads();
    for (int s = 128; s > 0; s >>= 1) { if (tid < s) red[tid] += red[tid + s]; __syncthreads(); }
    if (tid == 0) lser[r] = m + logf(red[0]);
}

__global__ void lse_col_k(const float* __restrict__ sim, float* __restrict__ lsec)
{
    int cg = blockIdx.x & 31;
    int p  = blockIdx.x >> 5;
    int tid = threadIdx.x;
    int jc = (tid & 31);
    int j = cg * 32 + jc;
    int rg = tid >> 5;
    const float* base = sim + (long)p * LGN * LGN + j;
    float m = -INFINITY, s = 0.0f;
    for (int i = rg; i < LGN; i += 8) {
        float v = base[(long)i * LGN];
        if (v > m) { s = s * expf(m - v) + 1.0f; m = v; }
        else s += expf(v - m);
    }
    __shared__ float sm[8][33], ss[8][33];
    sm[rg][jc] = m; ss[rg][jc] = s;
    __syncthreads();
    if (tid < 32) {
        float M = sm[0][tid], S = ss[0][tid];
#pragma unroll
        for (int g = 1; g < 8; g++) {
            float m2 = sm[g][tid], s2 = ss[g][tid];
            if (m2 > M) { S = S * expf(M - m2) + s2; M = m2; }
            else S += s2 * expf(m2 - M);
        }
        lsec[p * LGN + cg * 32 + tid] = M + logf(S);
    }
}

__device__ __forceinline__ float lsig(float t) {
    return fminf(t, 0.0f) - log1pf(expf(-fabsf(t)));
}

__global__ void scores_k(const float* __restrict__ sim, const float* __restrict__ lser,
                         const float* __restrict__ lsec, const float* __restrict__ z,
                         float* __restrict__ out)
{
    long idx = (long)blockIdx.x * 256 + threadIdx.x;
    if (idx >= (long)NN2) return;
    int j = idx & (LGN - 1);
    long r = idx >> 10;
    int i = (int)(r & (LGN - 1));
    int p = (int)(r >> 10);
    float zq = z[(2 * p) * LGN + i];
    float zk = z[(2 * p + 1) * LGN + j];
    out[idx] = 2.0f * sim[idx] - lser[p * LGN + i] - lsec[p * LGN + j] + lsig(zq) + lsig(zk);
}

__global__ void argmax_row_k(const float* __restrict__ S, float* __restrict__ rmax,
                             int* __restrict__ m0)
{
    long i = blockIdx.x;
    const float* p = S + i * LGN;
    int tid = threadIdx.x;
    float bv = -INFINITY; int bi = 0;
    for (int j = tid; j < LGN; j += 256) {
        float v = p[j];
        if (v > bv) { bv = v; bi = j; }
    }
    __shared__ float sv[256]; __shared__ int si[256];
    sv[tid] = bv; si[tid] = bi; __syncthreads();
    for (int s = 128; s > 0; s >>= 1) {
        if (tid < s) {
            float v2 = sv[tid + s]; int i2 = si[tid + s];
            if (v2 > sv[tid] || (v2 == sv[tid] && i2 < si[tid])) { sv[tid] = v2; si[tid] = i2; }
        }
        __syncthreads();
    }
    if (tid == 0) { rmax[i] = sv[0]; m0[i] = si[0]; }
}

__global__ void argmax_col_k(const float* __restrict__ S, int* __restrict__ m1)
{
    int cg = blockIdx.x;
    int tid = threadIdx.x;
    int jc = tid & 31;
    int j = cg * 32 + jc;
    int rg = tid >> 5;
    float bv = -INFINITY; int bi = 0;
    for (int i = rg; i < LGN; i += 8) {
        float v = S[(long)i * LGN + j];
        if (v > bv || (v == bv && i < bi)) { bv = v; bi = i; }
    }
    __shared__ float sv[8][33]; __shared__ int si[8][33];
    sv[rg][jc] = bv; si[rg][jc] = bi;
    __syncthreads();
    if (tid < 32) {
        float V = sv[0][tid]; int I = si[0][tid];
#pragma unroll
        for (int g = 1; g < 8; g++) {
            float v2 = sv[g][tid]; int i2 = si[g][tid];
            if (v2 > V || (v2 == V && i2 < I)) { V = v2; I = i2; }
        }
        m1[cg * 32 + tid] = I;
    }
}

__global__ void filter_k(const int* __restrict__ m0, const int* __restrict__ m1,
                         const float* __restrict__ rmax, float* __restrict__ out)
{
    __shared__ float vals[LGN];
    __shared__ float rv[LGN];
    __shared__ int   ri[LGN];
    int n = threadIdx.x;
    float ms = expf(rmax[n]);
    bool mutual = (m1[m0[n]] == n);
    vals[n] = (mutual && ms > 0.1f) ? ms : 0.0f;
    __syncthreads();
    for (int k = 0; k < 50; k++) {
        rv[n] = vals[n]; ri[n] = n; __syncthreads();
        for (int s = 512; s > 0; s >>= 1) {
            if (n < s) {
                float v2 = rv[n + s]; int i2 = ri[n + s];
                if (v2 > rv[n] || (v2 == rv[n] && i2 < ri[n])) { rv[n] = v2; ri[n] = i2; }
            }
            __syncthreads();
        }
        if (n == 0) {
            int bi = ri[0]; float bv = rv[0];
            out[NN2 + k * 3 + 0] = 0.0f;
            out[NN2 + k * 3 + 1] = (float)bi;
            out[NN2 + k * 3 + 2] = (float)m0[bi];
            out[NN2 + 150 + k]   = bv;
            vals[bi] = -1.0f;
        }
        __syncthreads();
    }
}

// -------------------- host-side launchers ----------------------------------
#define GSMEM128 ((128 + 128) * GSTR * 2 * 4)
#define GSMEM64  ((64 + 128) * GSTR * 2 * 4)

static void tgemm(const float* A, const float* B, float* C,
                  int M, int N, int K, int ldC,
                  long sA, long sB, long sC, int batch,
                  const float* bias, const float* res, float alpha,
                  float* C2, int rnd, int rndA)
{
    if (N > 512) {
        dim3 grid(N / 128, M / 128, batch);
        if (rndA)
            tgemm_k<128, 1, 0><<<grid, 256, GSMEM128>>>(A, B, C, M, N, K, ldC, sA, sB, sC,
                bias, res, alpha, C2, rnd, nullptr, nullptr, nullptr, nullptr, nullptr);
        else
            tgemm_k<128, 0, 0><<<grid, 256, GSMEM128>>>(A, B, C, M, N, K, ldC, sA, sB, sC,
                bias, res, alpha, C2, rnd, nullptr, nullptr, nullptr, nullptr, nullptr);
    } else {
        dim3 grid(N / 128, M / 64, batch);
        if (rndA)
            tgemm_k<64, 1, 0><<<grid, 128, GSMEM64>>>(A, B, C, M, N, K, ldC, sA, sB, sC,
                bias, res, alpha, C2, rnd, nullptr, nullptr, nullptr, nullptr, nullptr);
        else
            tgemm_k<64, 0, 0><<<grid, 128, GSMEM64>>>(A, B, C, M, N, K, ldC, sA, sB, sC,
                bias, res, alpha, C2, rnd, nullptr, nullptr, nullptr, nullptr, nullptr);
    }
}

extern "C" void kernel_launch(void* const* d_in, const int* in_sizes, int n_in,
                              void* d_out, int out_size)
{
    (void)in_sizes; (void)n_in; (void)out_size;
    const float* kpts      = (const float*)d_in[0];
    const float* desc      = (const float*)d_in[1];
    const float* posenc_Wr = (const float*)d_in[2];
    const float* sWqkv_w   = (const float*)d_in[3];
    const float* sWqkv_b   = (const float*)d_in[4];
    const float* sOut_w    = (const float*)d_in[5];
    const float* sOut_b    = (const float*)d_in[6];
    const float* sF1_w     = (const float*)d_in[7];
    const float* sF1_b     = (const float*)d_in[8];
    const float* sLN_g     = (const float*)d_in[9];
    const float* sLN_b     = (const float*)d_in[10];
    const float* sF2_w     = (const float*)d_in[11];
    const float* sF2_b     = (const float*)d_in[12];
    const float* cQK_w     = (const float*)d_in[13];
    const float* cQK_b     = (const float*)d_in[14];
    const float* cV_w      = (const float*)d_in[15];
    const float* cV_b      = (const float*)d_in[16];
    const float* cOut_w    = (const float*)d_in[17];
    const float* cOut_b    = (const float*)d_in[18];
    const float* cF1_w     = (const float*)d_in[19];
    const float* cF1_b     = (const float*)d_in[20];
    const float* cLN_g     = (const float*)d_in[21];
    const float* cLN_b     = (const float*)d_in[22];
    const float* cF2_w     = (const float*)d_in[23];
    const float* cF2_b     = (const float*)d_in[24];
    const float* fp_w      = (const float*)d_in[25];
    const float* fp_b      = (const float*)d_in[26];
    const float* match_w   = (const float*)d_in[27];
    const float* match_b   = (const float*)d_in[28];
    float* out = (float*)d_out;

    float *x, *Q, *K, *V, *ctx, *cat, *h1, *h2, *md, *sim, *z;
    float *lser, *lsec, *rmax, *wr;
    int *m0, *m1;
    cudaGetSymbolAddress((void**)&x,    g_x);
    cudaGetSymbolAddress((void**)&Q,    g_Q);
    cudaGetSymbolAddress((void**)&K,    g_K);
    cudaGetSymbolAddress((void**)&V,    g_V);
    cudaGetSymbolAddress((void**)&ctx,  g_ctx);
    cudaGetSymbolAddress((void**)&cat,  g_cat);
    cudaGetSymbolAddress((void**)&h1,   g_h1);
    cudaGetSymbolAddress((void**)&h2,   g_h2);
    cudaGetSymbolAddress((void**)&md,   g_md);
    cudaGetSymbolAddress((void**)&sim,  g_sim);
    cudaGetSymbolAddress((void**)&z,    g_z);
    cudaGetSymbolAddress((void**)&lser, g_lser);
    cudaGetSymbolAddress((void**)&lsec, g_lsec);
    cudaGetSymbolAddress((void**)&rmax, g_rmax);
    cudaGetSymbolAddress((void**)&m0,   g_m0);
    cudaGetSymbolAddress((void**)&m1,   g_m1);
    cudaGetSymbolAddress((void**)&wr,   g_wr);

    cudaFuncSetAttribute(flash_k, cudaFuncAttributeMaxDynamicSharedMemorySize, FSMEM);
    cudaFuncSetAttribute(tgemm_k<128, 0, 0>, cudaFuncAttributeMaxDynamicSharedMemorySize, GSMEM128);
    cudaFuncSetAttribute(tgemm_k<128, 1, 0>, cudaFuncAttributeMaxDynamicSharedMemorySize, GSMEM128);
    cudaFuncSetAttribute(tgemm_k<128, 1, 1>, cudaFuncAttributeMaxDynamicSharedMemorySize, GSMEM128);
    cudaFuncSetAttribute(tgemm_k<64, 0, 0>,  cudaFuncAttributeMaxDynamicSharedMemorySize, GSMEM64);
    cudaFuncSetAttribute(tgemm_k<64, 1, 0>,  cudaFuncAttributeMaxDynamicSharedMemorySize, GSMEM64);
    cudaFuncSetAttribute(tgemm_k<64, 1, 2>,  cudaFuncAttributeMaxDynamicSharedMemorySize, GSMEM64);

    // ---- weight prep: rounded (and permuted/packed) copies ----
    long off = 0;
    auto prep = [&](const float* src, long n) -> float* {
        float* d = wr + off; off += n;
        roundw4_k<<<(int)((n / 4 + 255) / 256), 256>>>((const float4*)src, (float4*)d,
                                                       (int)(n / 4));
        return d;
    };
    float* rqkvW = wr + off; off += (long)LGL * 768 * LGD;
    permqkv_k<<<(LGL * 768 * 64 + 255) / 256, 256>>>((const float4*)sWqkv_w,
                                                     (float4*)rqkvW);
    float* rsOut  = prep(sOut_w,  (long)LGL * LGD * LGD);
    float* rsF1   = prep(sF1_w,   (long)LGL * 4 * LGD * LGD);
    float* rsF2   = prep(sF2_w,   (long)LGL * 2 * LGD * LGD);
    float* rcqkvW = wr + off; off += (long)LGL * 512 * LGD;
    pack2_k<<<(LGL * 512 * 64 + 255) / 256, 256>>>((const float4*)cQK_w,
                                                   (const float4*)cV_w,
                                                   (float4*)rcqkvW);
    float* rcOut  = prep(cOut_w,  (long)LGL * LGD * LGD);
    float* rcF1   = prep(cF1_w,   (long)LGL * 4 * LGD * LGD);
    float* rcF2   = prep(cF2_w,   (long)LGL * 2 * LGD * LGD);
    float* rfp    = prep(fp_w,    (long)LGD * LGD);
    float* rqkvB = wr + off; off += (long)LGL * 768;
    permqkvb_k<<<(LGL * 768 + 255) / 256, 256>>>(sWqkv_b, rqkvB);
    float* rcqkvB = wr + off; off += (long)LGL * 512;
    pack2b_k<<<(LGL * 512 + 255) / 256, 256>>>(cQK_b, cV_b, rcqkvB);

    const long sSS = (long)LGN * LGN;

    copy2_k<<<(M4 * LGD + 255) / 256, 256>>>(desc, x, cat);

    for (int i = 0; i < LGL; i++) {
        // ---------------- self attention ----------------
        {
            dim3 grid(768 / 128, M4 / 128, 1);
            tgemm_k<128, 1, 1><<<grid, 256, GSMEM128>>>(
                x, rqkvW + (long)i * 768 * LGD, nullptr, M4, 768, LGD, 0,
                0, 0, 0, rqkvB + (long)i * 768, nullptr, 1.0f, nullptr, 0,
                Q, K, V, kpts, posenc_Wr);
        }
        flash_k<<<dim3(16, BH), 128, FSMEM>>>(Q, K, V, ctx, 0);
        tgemm(ctx, rsOut + (long)i * LGD * LGD, cat + LGD, M4, LGD, LGD, 2 * LGD,
              0, 0, 0, 1, sOut_b + (long)i * LGD, nullptr, 1.0f, nullptr, 1, 0);
        tgemm(cat, rsF1 + (long)i * 4 * LGD * LGD, h1, M4, 2 * LGD, 2 * LGD, 2 * LGD,
              0, 0, 0, 1, sF1_b + (long)i * 2 * LGD, nullptr, 1.0f, nullptr, 0, 0);
        lngelu_k<<<M4, 256>>>(h1, sLN_g + (long)i * 2 * LGD, sLN_b + (long)i * 2 * LGD, h2);
        tgemm(h2, rsF2 + (long)i * 2 * LGD * LGD, x, M4, LGD, 2 * LGD, LGD,
              0, 0, 0, 1, sF2_b + (long)i * LGD, x, 1.0f, cat, 2, 0);

        // ---------------- cross attention ----------------
        {
            dim3 grid(512 / 128, M4 / 64, 1);
            tgemm_k<64, 1, 2><<<grid, 128, GSMEM64>>>(
                x, rcqkvW + (long)i * 512 * LGD, nullptr, M4, 512, LGD, 0,
                0, 0, 0, rcqkvB + (long)i * 512, nullptr, 1.0f, nullptr, 0,
                Q, nullptr, V, nullptr, nullptr);
        }
        flash_k<<<dim3(16, BH), 128, FSMEM>>>(Q, Q, V, ctx, 4);
        tgemm(ctx, rcOut + (long)i * LGD * LGD, cat + LGD, M4, LGD, LGD, 2 * LGD,
              0, 0, 0, 1, cOut_b + (long)i * LGD, nullptr, 1.0f, nullptr, 1, 0);
        tgemm(cat, rcF1 + (long)i * 4 * LGD * LGD, h1, M4, 2 * LGD, 2 * LGD, 2 * LGD,
              0, 0, 0, 1, cF1_b + (long)i * 2 * LGD, nullptr, 1.0f, nullptr, 0, 0);
        lngelu_k<<<M4, 256>>>(h1, cLN_g + (long)i * 2 * LGD, cLN_b + (long)i * 2 * LGD, h2);
        tgemm(h2, rcF2 + (long)i * 2 * LGD * LGD, x, M4, LGD, 2 * LGD, LGD,
              0, 0, 0, 1, cF2_b + (long)i * LGD, x, 1.0f, cat, 2, 0);
    }

    // ---------------- matching head ----------------
    tgemm(x, rfp, md, M4, LGD, LGD, LGD, 0, 0, 0, 1, fp_b, nullptr, 0.25f,
          nullptr, 1, 1);
    tgemm(md, md + (long)LGN * LGD, sim, LGN, LGN, LGD, LGN,
          (long)2 * LGN * LGD, (long)2 * LGN * LGD, sSS, 2, nullptr, nullptr, 1.0f,
          nullptr, 0, 0);
    z_k<<<M4, 256>>>(x, match_w, match_b, z);
    lse_row_k<<<2 * LGN, 256>>>(sim, lser);
    lse_col_k<<<64, 256>>>(sim, lsec);
    scores_k<<<(NN2 + 255) / 256, 256>>>(sim, lser, lsec, z, out);

    // ---------------- filter (batch 0 only) ----------------
    argmax_row_k<<<LGN, 256>>>(out, rmax, m0);
    argmax_col_k<<<32, 256>>>(out, m1);
    filter_k<<<1, 1024>>>(m0, m1, rmax, out);
}

// round 17
// speedup vs baseline: 1.0805x; 1.0805x over previous
#include <cuda_runtime.h>
#include <cuda_bf16.h>
#include <math.h>
#include <stdint.h>

// ---------------------------------------------------------------------------
// LightGlue forward. L=9, D=256, H=4, HD=64, N=1024, B=4 (2 pairs).
// tf32 mma dense GEMMs with fused RoPE-split / head-split epilogues.
// Tile sizes: 128x128 (N>=768), 64x128 (N=512), 64x64 (N=256, full SM
// coverage). Flash attention: 64-key tiles, 89 KB smem, 2 CTAs/SM.
// ---------------------------------------------------------------------------

#define LGB   4
#define LGN   1024
#define LGD   256
#define LGH   4
#define LGHD  64
#define LGL   9
#define M4    (LGB*LGN)
#define BH    (LGB*LGH)
#define NN2   (2*1024*1024)

// -------------------- scratch (device globals; no allocation) --------------
__device__ float g_x   [M4*LGD];
__device__ float g_Q   [BH*LGN*LGHD];
__device__ float g_K   [BH*LGN*LGHD];
__device__ float g_V   [BH*LGN*LGHD];
__device__ float g_ctx [M4*LGD];
__device__ float g_cat [M4*2*LGD];
__device__ float g_h1  [M4*2*LGD];
__device__ float g_h2  [M4*2*LGD];
__device__ float g_md  [M4*LGD];
__device__ float g_sim [NN2];
__device__ float g_z   [M4];
__device__ float g_lser[2*LGN];
__device__ float g_lsec[2*LGN];
__device__ int   g_m0  [LGN];
__device__ int   g_m1  [LGN];
__device__ float g_rmax[LGN];
__device__ float g_wr  [11283712];        // tf32-rounded weights + biases

// -------------------- tf32 helpers -----------------------------------------
__device__ __forceinline__ uint32_t tf32u(float x) {
    uint32_t u;
    asm("cvt.rna.tf32.f32 %0, %1;" : "=r"(u) : "f"(x));
    return u;
}
__device__ __forceinline__ float tf32r(float x) { return __uint_as_float(tf32u(x)); }

__device__ __forceinline__ void mma_tf32(float (&d)[4], const uint32_t (&a)[4],
                                         const uint32_t (&b)[2]) {
    asm volatile(
        "mma.sync.aligned.m16n8k8.row.col.f32.tf32.tf32.f32 "
        "{%0,%1,%2,%3}, {%4,%5,%6,%7}, {%8,%9}, {%0,%1,%2,%3};"
        : "+f"(d[0]), "+f"(d[1]), "+f"(d[2]), "+f"(d[3])
        : "r"(a[0]), "r"(a[1]), "r"(a[2]), "r"(a[3]), "r"(b[0]), "r"(b[1]));
}

__device__ __forceinline__ void cp16(void* dst, const void* src) {
    uint32_t d = (uint32_t)__cvta_generic_to_shared(dst);
    asm volatile("cp.async.cg.shared.global [%0], [%1], 16;" :: "r"(d), "l"(src));
}
__device__ __forceinline__ void cp_commit() { asm volatile("cp.async.commit_group;"); }
template<int n> __device__ __forceinline__ void cp_wait() {
    asm volatile("cp.async.wait_group %0;" :: "n"(n));
}

// -------------------- weight prep kernels -----------------------------------
__global__ void roundw4_k(const float4* __restrict__ src, float4* __restrict__ dst,
                          int n4) {
    int i = blockIdx.x * blockDim.x + threadIdx.x;
    if (i >= n4) return;
    float4 v = src[i];
    v.x = tf32r(v.x); v.y = tf32r(v.y); v.z = tf32r(v.z); v.w = tf32r(v.w);
    dst[i] = v;
}

// qkv weight permute+round: src rows interleaved (out = 3d+sec) -> [q|k|v]
__global__ void permqkv_k(const float4* __restrict__ src, float4* __restrict__ dst) {
    int i = blockIdx.x * blockDim.x + threadIdx.x;       // LGL*768*64
    if (i >= LGL * 768 * 64) return;
    int k4 = i & 63;
    int row = (i >> 6) % 768;
    int l = i / (768 * 64);
    int sec = row >> 8, d = row & 255;
    float4 v = src[((long)l * 768 + 3 * d + sec) * 64 + k4];
    v.x = tf32r(v.x); v.y = tf32r(v.y); v.z = tf32r(v.z); v.w = tf32r(v.w);
    dst[i] = v;
}
__global__ void permqkvb_k(const float* __restrict__ src, float* __restrict__ dst) {
    int i = blockIdx.x * blockDim.x + threadIdx.x;       // LGL*768
    if (i >= LGL * 768) return;
    int row = i % 768, l = i / 768;
    int sec = row >> 8, d = row & 255;
    dst[i] = src[l * 768 + 3 * d + sec];
}

// pack cQK / cV weights into [qk|v] per layer, rounded
__global__ void pack2_k(const float4* __restrict__ a, const float4* __restrict__ b,
                        float4* __restrict__ dst) {
    int i = blockIdx.x * blockDim.x + threadIdx.x;       // LGL*512*64
    if (i >= LGL * 512 * 64) return;
    int k4 = i & 63;
    int row = (i >> 6) % 512;
    int l = i / (512 * 64);
    int sec = row >> 8, r = row & 255;
    const float4* s = sec ? b : a;
    float4 v = s[((long)l * 256 + r) * 64 + k4];
    v.x = tf32r(v.x); v.y = tf32r(v.y); v.z = tf32r(v.z); v.w = tf32r(v.w);
    dst[i] = v;
}
__global__ void pack2b_k(const float* __restrict__ a, const float* __restrict__ b,
                         float* __restrict__ dst) {
    int i = blockIdx.x * blockDim.x + threadIdx.x;       // LGL*512
    if (i >= LGL * 512) return;
    int row = i % 512, l = i / 512;
    dst[i] = (row >= 256) ? b[l * 256 + row - 256] : a[l * 256 + row];
}

// -------------------- dense tf32 GEMM (NT only) -----------------------------
// B pre-rounded. A pre-rounded iff RNDA==0.
// EPI=0: normal epilogue (C, optional C2, rnd).  alpha/res supported.
// EPI=1: qkv+RoPE epilogue -> writes Qo/Ko/Vo split-head, tf32-rounded.
// EPI=2: packed qk|v epilogue -> writes Qo/Vo split-head, tf32-rounded.
#define GSTR 36

template<int BM, int BN, int RNDA, int EPI>
__global__ void __launch_bounds__(BM * 2, (BM == 128) ? 2 : 3) tgemm_k(
    const float* __restrict__ A, const float* __restrict__ B, float* C,
    int M, int N, int K, int ldC,
    long sA, long sB, long sC,
    const float* __restrict__ bias, const float* res, float alpha,
    float* C2, int rnd,
    float* Qo, float* Ko, float* Vo,
    const float* __restrict__ kpts, const float* __restrict__ Wr)
{
    constexpr int THREADS = BM * 2;
    constexpr int WCOL = THREADS / 64;            // warp columns (4 or 2)
    constexpr int TM   = BM / 32;                 // m16 tiles per warp
    constexpr int TN   = BN / (WCOL * 8);         // n8 tiles per warp
    constexpr int ABUF = BM * GSTR;
    constexpr int BBUF = BN * GSTR;

    extern __shared__ float sm[];
    float* As = sm;
    float* Bs = sm + 2 * ABUF;

    int bh = blockIdx.z;
    A += (long)bh * sA;
    B += (long)bh * sB;
    if (EPI == 0) {
        C += (long)bh * sC;
        if (res) res += (long)bh * sC;
    }

    const int tid  = threadIdx.x;
    const int warp = tid >> 5, lane = tid & 31;
    const int wm = warp / WCOL, wn = warp % WCOL;
    const int gid = lane >> 2, tig = lane & 3;
    const int row0 = blockIdx.y * BM;
    const int col0 = blockIdx.x * BN;

    float acc[TM][TN][4];
#pragma unroll
    for (int i = 0; i < TM; i++)
#pragma unroll
        for (int j = 0; j < TN; j++)
#pragma unroll
            for (int q = 0; q < 4; q++) acc[i][j][q] = 0.0f;

#define LOADT(s, k0) do {                                                      \
    _Pragma("unroll")                                                          \
    for (int l = 0; l < BM * 8 / THREADS; l++) {                               \
        int v = tid + THREADS * l; int r = v >> 3; int off = (v & 7) * 4;      \
        cp16(&As[(s) * ABUF + r * GSTR + off],                                 \
             &A[(long)(row0 + r) * K + (k0) + off]);                           \
    }                                                                          \
    _Pragma("unroll")                                                          \
    for (int l = 0; l < BN * 8 / THREADS; l++) {                               \
        int v = tid + THREADS * l; int r = v >> 3; int off = (v & 7) * 4;      \
        cp16(&Bs[(s) * BBUF + r * GSTR + off],                                 \
             &B[(long)(col0 + r) * K + (k0) + off]);                           \
    }                                                                          \
    cp_commit(); } while (0)

    const int NK = K >> 5;
    LOADT(0, 0);

    for (int it = 0; it < NK; it++) {
        int cur = it & 1;
        cp_wait<0>();
        __syncthreads();
        if (it + 1 < NK) LOADT(cur ^ 1, (it + 1) << 5);
        const float* Ab = As + cur * ABUF;
        const float* Bb = Bs + cur * BBUF;

#pragma unroll
        for (int ks = 0; ks < 32; ks += 8) {
            uint32_t ar[TM][4];
#pragma unroll
            for (int tm = 0; tm < TM; tm++) {
                int mr = (wm * (TM * 16) + tm * 16 + gid) * GSTR;
                if (RNDA) {
                    ar[tm][0] = tf32u(Ab[mr + ks + tig]);
                    ar[tm][1] = tf32u(Ab[mr + 8 * GSTR + ks + tig]);
                    ar[tm][2] = tf32u(Ab[mr + ks + tig + 4]);
                    ar[tm][3] = tf32u(Ab[mr + 8 * GSTR + ks + tig + 4]);
                } else {
                    ar[tm][0] = __float_as_uint(Ab[mr + ks + tig]);
                    ar[tm][1] = __float_as_uint(Ab[mr + 8 * GSTR + ks + tig]);
                    ar[tm][2] = __float_as_uint(Ab[mr + ks + tig + 4]);
                    ar[tm][3] = __float_as_uint(Ab[mr + 8 * GSTR + ks + tig + 4]);
                }
            }
            uint32_t br[TN][2];
#pragma unroll
            for (int tn = 0; tn < TN; tn++) {
                int nr = (wn * (TN * 8) + tn * 8 + gid) * GSTR;
                br[tn][0] = __float_as_uint(Bb[nr + ks + tig]);
                br[tn][1] = __float_as_uint(Bb[nr + ks + tig + 4]);
            }
#pragma unroll
            for (int tm = 0; tm < TM; tm++)
#pragma unroll
                for (int tn = 0; tn < TN; tn++)
                    mma_tf32(acc[tm][tn], ar[tm], br[tn]);
        }
        __syncthreads();
    }
#undef LOADT

    if (EPI == 0) {
#pragma unroll
        for (int tm = 0; tm < TM; tm++) {
            int r0 = row0 + wm * (TM * 16) + tm * 16 + gid;
#pragma unroll
            for (int tn = 0; tn < TN; tn++) {
                int c = col0 + wn * (TN * 8) + tn * 8 + tig * 2;
                float b0 = bias ? bias[c] : 0.0f;
                float b1 = bias ? bias[c + 1] : 0.0f;
#pragma unroll
                for (int half = 0; half < 2; half++) {
                    int r = r0 + half * 8;
                    float v0 = (acc[tm][tn][half * 2 + 0] + b0) * alpha;
                    float v1 = (acc[tm][tn][half * 2 + 1] + b1) * alpha;
                    if (res) {
                        v0 += res[(long)r * ldC + c];
                        v1 += res[(long)r * ldC + c + 1];
                    }
                    float u0 = v0, u1 = v1;
                    if (rnd & 1) { v0 = tf32r(v0); v1 = tf32r(v1); }
                    *reinterpret_cast<float2*>(&C[(long)r * ldC + c]) = make_float2(v0, v1);
                    if (C2) {
                        if (rnd & 2) { u0 = tf32r(u0); u1 = tf32r(u1); }
                        else         { u0 = v0; u1 = v1; }
                        *reinterpret_cast<float2*>(&C2[(long)r * 512 + c]) = make_float2(u0, u1);
                    }
                }
            }
        }
    } else {
        // split-head (+RoPE for EPI=1) epilogue
#pragma unroll
        for (int tm = 0; tm < TM; tm++) {
            int r0 = row0 + wm * (TM * 16) + tm * 16 + gid;
#pragma unroll
            for (int tn = 0; tn < TN; tn++) {
                int c = col0 + wn * (TN * 8) + tn * 8 + tig * 2;
                int sec = c >> 8;
                int d = c & 255;
                int h = d >> 6, e = d & 63;
                float b0 = bias[c], b1 = bias[c + 1];
                float w0 = 0.0f, w1 = 0.0f;
                if (EPI == 1 && sec < 2) {
                    int f = e >> 1;
                    w0 = Wr[2 * f]; w1 = Wr[2 * f + 1];
                }
#pragma unroll
                for (int half = 0; half < 2; half++) {
                    int r = r0 + half * 8;
                    float v0 = acc[tm][tn][half * 2 + 0] + b0;
                    float v1 = acc[tm][tn][half * 2 + 1] + b1;
                    int b_ = r >> 10, n = r & (LGN - 1);
                    long base = (((long)(b_ * LGH + h)) * LGN + n) * LGHD + e;
                    if (EPI == 1) {
                        if (sec < 2) {
                            float kx = kpts[r * 2], ky = kpts[r * 2 + 1];
                            float pr = kx * w0 + ky * w1;
                            float co = cosf(pr), si = sinf(pr);
                            float* dst = (sec == 0) ? Qo : Ko;
                            dst[base]     = tf32r(co * v0 - si * v1);
                            dst[base + 1] = tf32r(co * v1 + si * v0);
                        } else {
                            Vo[base]     = tf32r(v0);
                            Vo[base + 1] = tf32r(v1);
                        }
                    } else {
                        float* dst = (sec == 0) ? Qo : Vo;
                        dst[base]     = tf32r(v0);
                        dst[base + 1] = tf32r(v1);
                    }
                }
            }
        }
    }
}

// -------------------- fused flash attention ---------------------------------
// Q,K,V pre-rounded tf32, [16 heads][1024][64]. ctx out merged, rounded.
// 64-query CTAs (4 warps x 16 rows), 64-key tiles, 89 KB smem, 2 CTAs/SM.
#define FKS 68
#define FVS 72
#define FKBUF (64*FKS)
#define FVBUF (64*FVS)
#define FSMEM ((2*FKBUF + 2*FVBUF + 64*FKS) * 4)   // 89088 bytes

__global__ void __launch_bounds__(128, 2) flash_k(
    const float* __restrict__ Qg, const float* __restrict__ Kg,
    const float* __restrict__ Vg, float* __restrict__ ctx, int xorB)
{
    extern __shared__ float smf[];
    float* Ksm = smf;                         // [2][64][68]
    float* Vsm = smf + 2 * FKBUF;             // [2][64][72]
    float* Ps  = smf + 2 * FKBUF + 2 * FVBUF; // [64][68]

    const int bh = blockIdx.y, qt = blockIdx.x;
    const float* Qh = Qg + (long)bh * (LGN * LGHD);
    const float* Kh = Kg + (long)(bh ^ xorB) * (LGN * LGHD);
    const float* Vh = Vg + (long)(bh ^ xorB) * (LGN * LGHD);

    const int tid = threadIdx.x, warp = tid >> 5, lane = tid & 31;
    const int gid = lane >> 2, tig = lane & 3;
    const int wrow = warp * 16;

#pragma unroll
    for (int l = 0; l < 8; l++) {
        int v = tid + 128 * l;
        int r = v >> 4, c = (v & 15) * 4;
        float4 q = *(const float4*)&Qh[(long)(qt * 64 + r) * LGHD + c];
        Ps[r * FKS + c]     = 0.125f * q.x; Ps[r * FKS + c + 1] = 0.125f * q.y;
        Ps[r * FKS + c + 2] = 0.125f * q.z; Ps[r * FKS + c + 3] = 0.125f * q.w;
    }
    __syncthreads();
    uint32_t qa[8][4];
#pragma unroll
    for (int ks = 0; ks < 8; ks++) {
        int k = ks * 8;
        qa[ks][0] = __float_as_uint(Ps[(wrow + gid) * FKS + k + tig]);
        qa[ks][1] = __float_as_uint(Ps[(wrow + gid + 8) * FKS + k + tig]);
        qa[ks][2] = __float_as_uint(Ps[(wrow + gid) * FKS + k + tig + 4]);
        qa[ks][3] = __float_as_uint(Ps[(wrow + gid + 8) * FKS + k + tig + 4]);
    }

    float oacc[8][4];
#pragma unroll
    for (int nt = 0; nt < 8; nt++)
#pragma unroll
        for (int j = 0; j < 4; j++) oacc[nt][j] = 0.0f;
    float mrow0 = -INFINITY, mrow1 = -INFINITY, lrow0 = 0.0f, lrow1 = 0.0f;

#define LOADKV(s, kt) do {                                                     \
    _Pragma("unroll")                                                          \
    for (int l = 0; l < 8; l++) {                                              \
        int v = tid + 128 * l; int r = v >> 4; int c = (v & 15) * 4;           \
        cp16(&Ksm[(s) * FKBUF + r * FKS + c],                                  \
             &Kh[(long)((kt) * 64 + r) * LGHD + c]);                           \
    }                                                                          \
    _Pragma("unroll")                                                          \
    for (int l = 0; l < 8; l++) {                                              \
        int v = tid + 128 * l; int r = v >> 4; int c = (v & 15) * 4;           \
        cp16(&Vsm[(s) * FVBUF + r * FVS + c],                                  \
             &Vh[(long)((kt) * 64 + r) * LGHD + c]);                           \
    }                                                                          \
    cp_commit(); } while (0)

    LOADKV(0, 0);

    for (int kt = 0; kt < 16; kt++) {
        int cur = kt & 1;
        cp_wait<0>();
        __syncthreads();
        if (kt + 1 < 16) LOADKV(cur ^ 1, kt + 1);
        const float* K_ = Ksm + cur * FKBUF;
        const float* V_ = Vsm + cur * FVBUF;

        float sacc[8][4];
#pragma unroll
        for (int nt = 0; nt < 8; nt++)
#pragma unroll
            for (int j = 0; j < 4; j++) sacc[nt][j] = 0.0f;
#pragma unroll
        for (int ks = 0; ks < 8; ks++) {
            int k = ks * 8;
#pragma unroll
            for (int nt = 0; nt < 8; nt++) {
                uint32_t b[2];
                b[0] = __float_as_uint(K_[(nt * 8 + gid) * FKS + k + tig]);
                b[1] = __float_as_uint(K_[(nt * 8 + gid) * FKS + k + tig + 4]);
                mma_tf32(sacc[nt], qa[ks], b);
            }
        }

        float t0 = -INFINITY, t1 = -INFINITY;
#pragma unroll
        for (int nt = 0; nt < 8; nt++) {
            t0 = fmaxf(t0, fmaxf(sacc[nt][0], sacc[nt][1]));
            t1 = fmaxf(t1, fmaxf(sacc[nt][2], sacc[nt][3]));
        }
        t0 = fmaxf(t0, __shfl_xor_sync(0xffffffffu, t0, 1));
        t0 = fmaxf(t0, __shfl_xor_sync(0xffffffffu, t0, 2));
        t1 = fmaxf(t1, __shfl_xor_sync(0xffffffffu, t1, 1));
        t1 = fmaxf(t1, __shfl_xor_sync(0xffffffffu, t1, 2));
        float mn0 = fmaxf(mrow0, t0), mn1 = fmaxf(mrow1, t1);
        float al0 = __expf(mrow0 - mn0), al1 = __expf(mrow1 - mn1);
        float s0 = 0.0f, s1 = 0.0f;
#pragma unroll
        for (int nt = 0; nt < 8; nt++) {
            sacc[nt][0] = __expf(sacc[nt][0] - mn0);
            sacc[nt][1] = __expf(sacc[nt][1] - mn0);
            sacc[nt][2] = __expf(sacc[nt][2] - mn1);
            sacc[nt][3] = __expf(sacc[nt][3] - mn1);
            s0 += sacc[nt][0] + sacc[nt][1];
            s1 += sacc[nt][2] + sacc[nt][3];
        }
        s0 += __shfl_xor_sync(0xffffffffu, s0, 1);
        s0 += __shfl_xor_sync(0xffffffffu, s0, 2);
        s1 += __shfl_xor_sync(0xffffffffu, s1, 1);
        s1 += __shfl_xor_sync(0xffffffffu, s1, 2);
        lrow0 = lrow0 * al0 + s0;
        lrow1 = lrow1 * al1 + s1;
        mrow0 = mn0; mrow1 = mn1;

#pragma unroll
        for (int nt = 0; nt < 8; nt++) {
            oacc[nt][0] *= al0; oacc[nt][1] *= al0;
            oacc[nt][2] *= al1; oacc[nt][3] *= al1;
            int c = nt * 8 + 2 * tig;
            Ps[(wrow + gid) * FKS + c]         = __uint_as_float(tf32u(sacc[nt][0]));
            Ps[(wrow + gid) * FKS + c + 1]     = __uint_as_float(tf32u(sacc[nt][1]));
            Ps[(wrow + gid + 8) * FKS + c]     = __uint_as_float(tf32u(sacc[nt][2]));
            Ps[(wrow + gid + 8) * FKS + c + 1] = __uint_as_float(tf32u(sacc[nt][3]));
        }
        __syncwarp();

#pragma unroll
        for (int ks = 0; ks < 8; ks++) {
            int k = ks * 8;
            uint32_t pa[4];
            pa[0] = __float_as_uint(Ps[(wrow + gid) * FKS + k + tig]);
            pa[1] = __float_as_uint(Ps[(wrow + gid + 8) * FKS + k + tig]);
            pa[2] = __float_as_uint(Ps[(wrow + gid) * FKS + k + tig + 4]);
            pa[3] = __float_as_uint(Ps[(wrow + gid + 8) * FKS + k + tig + 4]);
#pragma unroll
            for (int nt = 0; nt < 8; nt++) {
                uint32_t b[2];
                b[0] = __float_as_uint(V_[(k + tig) * FVS + nt * 8 + gid]);
                b[1] = __float_as_uint(V_[(k + tig + 4) * FVS + nt * 8 + gid]);
                mma_tf32(oacc[nt], pa, b);
            }
        }
        __syncthreads();
    }
#undef LOADKV

    float inv0 = 1.0f / lrow0, inv1 = 1.0f / lrow1;
    int b_ = bh >> 2, h = bh & 3;
    int n0 = qt * 64 + wrow + gid;
    long base0 = ((long)(b_ * LGN + n0)) * LGD + h * 64;
    long base1 = base0 + 8L * LGD;
#pragma unroll
    for (int nt = 0; nt < 8; nt++) {
        int c = nt * 8 + 2 * tig;
        *(float2*)&ctx[base0 + c] =
            make_float2(tf32r(oacc[nt][0] * inv0), tf32r(oacc[nt][1] * inv0));
        *(float2*)&ctx[base1 + c] =
            make_float2(tf32r(oacc[nt][2] * inv1), tf32r(oacc[nt][3] * inv1));
    }
}

// -------------------- elementwise / reduction kernels ----------------------
__global__ void copy2_k(const float* __restrict__ src, float* __restrict__ x,
                        float* __restrict__ cat) {
    int i = blockIdx.x * blockDim.x + threadIdx.x;
    if (i >= M4 * LGD) return;
    float v = src[i];
    x[i] = v;
    int r = i >> 8, c = i & 255;
    cat[(long)r * 512 + c] = tf32r(v);
}

// LayerNorm(512) + exact GELU; warp-shuffle reduction; output tf32-rounded.
__global__ void lngelu_k(const float* __restrict__ h, const float* __restrict__ g,
                         const float* __restrict__ bb, float* __restrict__ o)
{
    long row = blockIdx.x;
    int tid = threadIdx.x;
    int lane = tid & 31, warp = tid >> 5;
    const float* p = h + row * 512;
    float x0 = p[tid], x1 = p[tid + 256];
    float s1 = x0 + x1, s2 = x0 * x0 + x1 * x1;
#pragma unroll
    for (int off = 16; off > 0; off >>= 1) {
        s1 += __shfl_xor_sync(0xffffffffu, s1, off);
        s2 += __shfl_xor_sync(0xffffffffu, s2, off);
    }
    __shared__ float sm1[8], sm2[8];
    if (lane == 0) { sm1[warp] = s1; sm2[warp] = s2; }
    __syncthreads();
    float t1 = 0.0f, t2 = 0.0f;
#pragma unroll
    for (int w = 0; w < 8; w++) { t1 += sm1[w]; t2 += sm2[w]; }
    float mean = t1 * (1.0f / 512.0f);
    float var  = t2 * (1.0f / 512.0f) - mean * mean;
    float rr = rsqrtf(var + 1e-5f);
    float n0 = (x0 - mean) * rr * g[tid] + bb[tid];
    float n1 = (x1 - mean) * rr * g[tid + 256] + bb[tid + 256];
    o[row * 512 + tid]       = tf32r(0.5f * n0 * (1.0f + erff(n0 * 0.70710678118654752f)));
    o[row * 512 + tid + 256] = tf32r(0.5f * n1 * (1.0f + erff(n1 * 0.70710678118654752f)));
}

__global__ void z_k(const float* __restrict__ x, const float* __restrict__ w,
                    const float* __restrict__ b, float* __restrict__ z)
{
    long row = blockIdx.x;
    int tid = threadIdx.x;
    __shared__ float red[256];
    red[tid] = x[row * LGD + tid] * w[tid];
    __syncthreads();
    for (int s = 128; s > 0; s >>= 1) { if (tid < s) red[tid] += red[tid + s]; __syncthreads(); }
    if (tid == 0) z[row] = red[0] + b[0];
}

__global__ void lse_row_k(const float* __restrict__ sim, float* __restrict__ lser)
{
    long r = blockIdx.x;
    const float* p = sim + r * LGN;
    int tid = threadIdx.x;
    __shared__ float red[256];
    float m = -INFINITY;
    for (int j = tid; j < LGN; j += 256) m = fmaxf(m, p[j]);
    red[tid] = m; __syncthreads();
    for (int s = 128; s > 0; s >>= 1) { if (tid < s) red[tid] = fmaxf(red[tid], red[tid + s]); __syncthreads(); }
    m = red[0];
    __syncthreads();
    float sum = 0.0f;
    for (int j = tid; j < LGN; j += 256) sum += expf(p[j] - m);
    red[tid] = sum; __syncthreads();
    for (int s = 128; s > 0; s >>= 1) { if (tid < s) red[tid] += red[tid + s]; __syncthreads(); }
    if (tid == 0) lser[r] = m + logf(red[0]);
}

__global__ void lse_col_k(const float* __restrict__ sim, float* __restrict__ lsec)
{
    int cg = blockIdx.x & 31;
    int p  = blockIdx.x >> 5;
    int tid = threadIdx.x;
    int jc = (tid & 31);
    int j = cg * 32 + jc;
    int rg = tid >> 5;
    const float* base = sim + (long)p * LGN * LGN + j;
    float m = -INFINITY, s = 0.0f;
    for (int i = rg; i < LGN; i += 8) {
        float v = base[(long)i * LGN];
        if (v > m) { s = s * expf(m - v) + 1.0f; m = v; }
        else s += expf(v - m);
    }
    __shared__ float sm[8][33], ss[8][33];
    sm[rg][jc] = m; ss[rg][jc] = s;
    __syncthreads();
    if (tid < 32) {
        float M = sm[0][tid], S = ss[0][tid];
#pragma unroll
        for (int g = 1; g < 8; g++) {
            float m2 = sm[g][tid], s2 = ss[g][tid];
            if (m2 > M) { S = S * expf(M - m2) + s2; M = m2; }
            else S += s2 * expf(m2 - M);
        }
        lsec[p * LGN + cg * 32 + tid] = M + logf(S);
    }
}

__device__ __forceinline__ float lsig(float t) {
    return fminf(t, 0.0f) - log1pf(expf(-fabsf(t)));
}

__global__ void scores_k(const float* __restrict__ sim, const float* __restrict__ lser,
                         const float* __restrict__ lsec, const float* __restrict__ z,
                         float* __restrict__ out)
{
    long idx = (long)blockIdx.x * 256 + threadIdx.x;
    if (idx >= (long)NN2) return;
    int j = idx & (LGN - 1);
    long r = idx >> 10;
    int i = (int)(r & (LGN - 1));
    int p = (int)(r >> 10);
    float zq = z[(2 * p) * LGN + i];
    float zk = z[(2 * p + 1) * LGN + j];
    out[idx] = 2.0f * sim[idx] - lser[p * LGN + i] - lsec[p * LGN + j] + lsig(zq) + lsig(zk);
}

__global__ void argmax_row_k(const float* __restrict__ S, float* __restrict__ rmax,
                             int* __restrict__ m0)
{
    long i = blockIdx.x;
    const float* p = S + i * LGN;
    int tid = threadIdx.x;
    float bv = -INFINITY; int bi = 0;
    for (int j = tid; j < LGN; j += 256) {
        float v = p[j];
        if (v > bv) { bv = v; bi = j; }
    }
    __shared__ float sv[256]; __shared__ int si[256];
    sv[tid] = bv; si[tid] = bi; __syncthreads();
    for (int s = 128; s > 0; s >>= 1) {
        if (tid < s) {
            float v2 = sv[tid + s]; int i2 = si[tid + s];
            if (v2 > sv[tid] || (v2 == sv[tid] && i2 < si[tid])) { sv[tid] = v2; si[tid] = i2; }
        }
        __syncthreads();
    }
    if (tid == 0) { rmax[i] = sv[0]; m0[i] = si[0]; }
}

__global__ void argmax_col_k(const float* __restrict__ S, int* __restrict__ m1)
{
    int cg = blockIdx.x;
    int tid = threadIdx.x;
    int jc = tid & 31;
    int j = cg * 32 + jc;
    int rg = tid >> 5;
    float bv = -INFINITY; int bi = 0;
    for (int i = rg; i < LGN; i += 8) {
        float v = S[(long)i * LGN + j];
        if (v > bv || (v == bv && i < bi)) { bv = v; bi = i; }
    }
    __shared__ float sv[8][33]; __shared__ int si[8][33];
    sv[rg][jc] = bv; si[rg][jc] = bi;
    __syncthreads();
    if (tid < 32) {
        float V = sv[0][tid]; int I = si[0][tid];
#pragma unroll
        for (int g = 1; g < 8; g++) {
            float v2 = sv[g][tid]; int i2 = si[g][tid];
            if (v2 > V || (v2 == V && i2 < I)) { V = v2; I = i2; }
        }
        m1[cg * 32 + tid] = I;
    }
}

__global__ void filter_k(const int* __restrict__ m0, const int* __restrict__ m1,
                         const float* __restrict__ rmax, float* __restrict__ out)
{
    __shared__ float vals[LGN];
    __shared__ float rv[LGN];
    __shared__ int   ri[LGN];
    int n = threadIdx.x;
    float ms = expf(rmax[n]);
    bool mutual = (m1[m0[n]] == n);
    vals[n] = (mutual && ms > 0.1f) ? ms : 0.0f;
    __syncthreads();
    for (int k = 0; k < 50; k++) {
        rv[n] = vals[n]; ri[n] = n; __syncthreads();
        for (int s = 512; s > 0; s >>= 1) {
            if (n < s) {
                float v2 = rv[n + s]; int i2 = ri[n + s];
                if (v2 > rv[n] || (v2 == rv[n] && i2 < ri[n])) { rv[n] = v2; ri[n] = i2; }
            }
            __syncthreads();
        }
        if (n == 0) {
            int bi = ri[0]; float bv = rv[0];
            out[NN2 + k * 3 + 0] = 0.0f;
            out[NN2 + k * 3 + 1] = (float)bi;
            out[NN2 + k * 3 + 2] = (float)m0[bi];
            out[NN2 + 150 + k]   = bv;
            vals[bi] = -1.0f;
        }
        __syncthreads();
    }
}

// -------------------- host-side launchers ----------------------------------
#define GSMEM_(BM, BN) (2 * ((BM) + (BN)) * GSTR * 4)
#define GSMEM128 GSMEM_(128, 128)
#define GSMEM64  GSMEM_(64, 128)
#define GSMEM6464 GSMEM_(64, 64)

static void tgemm(const float* A, const float* B, float* C,
                  int M, int N, int K, int ldC,
                  long sA, long sB, long sC, int batch,
                  const float* bias, const float* res, float alpha,
                  float* C2, int rnd, int rndA)
{
    if (N > 512) {
        dim3 grid(N / 128, M / 128, batch);
        if (rndA)
            tgemm_k<128, 128, 1, 0><<<grid, 256, GSMEM128>>>(A, B, C, M, N, K, ldC, sA, sB, sC,
                bias, res, alpha, C2, rnd, nullptr, nullptr, nullptr, nullptr, nullptr);
        else
            tgemm_k<128, 128, 0, 0><<<grid, 256, GSMEM128>>>(A, B, C, M, N, K, ldC, sA, sB, sC,
                bias, res, alpha, C2, rnd, nullptr, nullptr, nullptr, nullptr, nullptr);
    } else if (N > 256) {
        dim3 grid(N / 128, M / 64, batch);
        if (rndA)
            tgemm_k<64, 128, 1, 0><<<grid, 128, GSMEM64>>>(A, B, C, M, N, K, ldC, sA, sB, sC,
                bias, res, alpha, C2, rnd, nullptr, nullptr, nullptr, nullptr, nullptr);
        else
            tgemm_k<64, 128, 0, 0><<<grid, 128, GSMEM64>>>(A, B, C, M, N, K, ldC, sA, sB, sC,
                bias, res, alpha, C2, rnd, nullptr, nullptr, nullptr, nullptr, nullptr);
    } else {
        // N == 256: 64x64 tiles -> grid(4, 64) = 256 CTAs (full SM coverage)
        dim3 grid(N / 64, M / 64, batch);
        if (rndA)
            tgemm_k<64, 64, 1, 0><<<grid, 128, GSMEM6464>>>(A, B, C, M, N, K, ldC, sA, sB, sC,
                bias, res, alpha, C2, rnd, nullptr, nullptr, nullptr, nullptr, nullptr);
        else
            tgemm_k<64, 64, 0, 0><<<grid, 128, GSMEM6464>>>(A, B, C, M, N, K, ldC, sA, sB, sC,
                bias, res, alpha, C2, rnd, nullptr, nullptr, nullptr, nullptr, nullptr);
    }
}

extern "C" void kernel_launch(void* const* d_in, const int* in_sizes, int n_in,
                              void* d_out, int out_size)
{
    (void)in_sizes; (void)n_in; (void)out_size;
    const float* kpts      = (const float*)d_in[0];
    const float* desc      = (const float*)d_in[1];
    const float* posenc_Wr = (const float*)d_in[2];
    const float* sWqkv_w   = (const float*)d_in[3];
    const float* sWqkv_b   = (const float*)d_in[4];
    const float* sOut_w    = (const float*)d_in[5];
    const float* sOut_b    = (const float*)d_in[6];
    const float* sF1_w     = (const float*)d_in[7];
    const float* sF1_b     = (const float*)d_in[8];
    const float* sLN_g     = (const float*)d_in[9];
    const float* sLN_b     = (const float*)d_in[10];
    const float* sF2_w     = (const float*)d_in[11];
    const float* sF2_b     = (const float*)d_in[12];
    const float* cQK_w     = (const float*)d_in[13];
    const float* cQK_b     = (const float*)d_in[14];
    const float* cV_w      = (const float*)d_in[15];
    const float* cV_b      = (const float*)d_in[16];
    const float* cOut_w    = (const float*)d_in[17];
    const float* cOut_b    = (const float*)d_in[18];
    const float* cF1_w     = (const float*)d_in[19];
    const float* cF1_b     = (const float*)d_in[20];
    const float* cLN_g     = (const float*)d_in[21];
    const float* cLN_b     = (const float*)d_in[22];
    const float* cF2_w     = (const float*)d_in[23];
    const float* cF2_b     = (const float*)d_in[24];
    const float* fp_w      = (const float*)d_in[25];
    const float* fp_b      = (const float*)d_in[26];
    const float* match_w   = (const float*)d_in[27];
    const float* match_b   = (const float*)d_in[28];
    float* out = (float*)d_out;

    float *x, *Q, *K, *V, *ctx, *cat, *h1, *h2, *md, *sim, *z;
    float *lser, *lsec, *rmax, *wr;
    int *m0, *m1;
    cudaGetSymbolAddress((void**)&x,    g_x);
    cudaGetSymbolAddress((void**)&Q,    g_Q);
    cudaGetSymbolAddress((void**)&K,    g_K);
    cudaGetSymbolAddress((void**)&V,    g_V);
    cudaGetSymbolAddress((void**)&ctx,  g_ctx);
    cudaGetSymbolAddress((void**)&cat,  g_cat);
    cudaGetSymbolAddress((void**)&h1,   g_h1);
    cudaGetSymbolAddress((void**)&h2,   g_h2);
    cudaGetSymbolAddress((void**)&md,   g_md);
    cudaGetSymbolAddress((void**)&sim,  g_sim);
    cudaGetSymbolAddress((void**)&z,    g_z);
    cudaGetSymbolAddress((void**)&lser, g_lser);
    cudaGetSymbolAddress((void**)&lsec, g_lsec);
    cudaGetSymbolAddress((void**)&rmax, g_rmax);
    cudaGetSymbolAddress((void**)&m0,   g_m0);
    cudaGetSymbolAddress((void**)&m1,   g_m1);
    cudaGetSymbolAddress((void**)&wr,   g_wr);

    cudaFuncSetAttribute(flash_k, cudaFuncAttributeMaxDynamicSharedMemorySize, FSMEM);
    cudaFuncSetAttribute(tgemm_k<128, 128, 0, 0>, cudaFuncAttributeMaxDynamicSharedMemorySize, GSMEM128);
    cudaFuncSetAttribute(tgemm_k<128, 128, 1, 0>, cudaFuncAttributeMaxDynamicSharedMemorySize, GSMEM128);
    cudaFuncSetAttribute(tgemm_k<128, 128, 1, 1>, cudaFuncAttributeMaxDynamicSharedMemorySize, GSMEM128);
    cudaFuncSetAttribute(tgemm_k<64, 128, 0, 0>,  cudaFuncAttributeMaxDynamicSharedMemorySize, GSMEM64);
    cudaFuncSetAttribute(tgemm_k<64, 128, 1, 0>,  cudaFuncAttributeMaxDynamicSharedMemorySize, GSMEM64);
    cudaFuncSetAttribute(tgemm_k<64, 128, 1, 2>,  cudaFuncAttributeMaxDynamicSharedMemorySize, GSMEM64);
    cudaFuncSetAttribute(tgemm_k<64, 64, 0, 0>,   cudaFuncAttributeMaxDynamicSharedMemorySize, GSMEM6464);
    cudaFuncSetAttribute(tgemm_k<64, 64, 1, 0>,   cudaFuncAttributeMaxDynamicSharedMemorySize, GSMEM6464);

    // ---- weight prep: rounded (and permuted/packed) copies ----
    long off = 0;
    auto prep = [&](const float* src, long n) -> float* {
        float* d = wr + off; off += n;
        roundw4_k<<<(int)((n / 4 + 255) / 256), 256>>>((const float4*)src, (float4*)d,
                                                       (int)(n / 4));
        return d;
    };
    float* rqkvW = wr + off; off += (long)LGL * 768 * LGD;
    permqkv_k<<<(LGL * 768 * 64 + 255) / 256, 256>>>((const float4*)sWqkv_w,
                                                     (float4*)rqkvW);
    float* rsOut  = prep(sOut_w,  (long)LGL * LGD * LGD);
    float* rsF1   = prep(sF1_w,   (long)LGL * 4 * LGD * LGD);
    float* rsF2   = prep(sF2_w,   (long)LGL * 2 * LGD * LGD);
    float* rcqkvW = wr + off; off += (long)LGL * 512 * LGD;
    pack2_k<<<(LGL * 512 * 64 + 255) / 256, 256>>>((const float4*)cQK_w,
                                                   (const float4*)cV_w,
                                                   (float4*)rcqkvW);
    float* rcOut  = prep(cOut_w,  (long)LGL * LGD * LGD);
    float* rcF1   = prep(cF1_w,   (long)LGL * 4 * LGD * LGD);
    float* rcF2   = prep(cF2_w,   (long)LGL * 2 * LGD * LGD);
    float* rfp    = prep(fp_w,    (long)LGD * LGD);
    float* rqkvB = wr + off; off += (long)LGL * 768;
    permqkvb_k<<<(LGL * 768 + 255) / 256, 256>>>(sWqkv_b, rqkvB);
    float* rcqkvB = wr + off; off += (long)LGL * 512;
    pack2b_k<<<(LGL * 512 + 255) / 256, 256>>>(cQK_b, cV_b, rcqkvB);

    const long sSS = (long)LGN * LGN;

    copy2_k<<<(M4 * LGD + 255) / 256, 256>>>(desc, x, cat);

    for (int i = 0; i < LGL; i++) {
        // ---------------- self attention ----------------
        {
            dim3 grid(768 / 128, M4 / 128, 1);
            tgemm_k<128, 128, 1, 1><<<grid, 256, GSMEM128>>>(
                x, rqkvW + (long)i * 768 * LGD, nullptr, M4, 768, LGD, 0,
                0, 0, 0, rqkvB + (long)i * 768, nullptr, 1.0f, nullptr, 0,
                Q, K, V, kpts, posenc_Wr);
        }
        flash_k<<<dim3(16, BH), 128, FSMEM>>>(Q, K, V, ctx, 0);
        tgemm(ctx, rsOut + (long)i * LGD * LGD, cat + LGD, M4, LGD, LGD, 2 * LGD,
              0, 0, 0, 1, sOut_b + (long)i * LGD, nullptr, 1.0f, nullptr, 1, 0);
        tgemm(cat, rsF1 + (long)i * 4 * LGD * LGD, h1, M4, 2 * LGD, 2 * LGD, 2 * LGD,
              0, 0, 0, 1, sF1_b + (long)i * 2 * LGD, nullptr, 1.0f, nullptr, 0, 0);
        lngelu_k<<<M4, 256>>>(h1, sLN_g + (long)i * 2 * LGD, sLN_b + (long)i * 2 * LGD, h2);
        tgemm(h2, rsF2 + (long)i * 2 * LGD * LGD, x, M4, LGD, 2 * LGD, LGD,
              0, 0, 0, 1, sF2_b + (long)i * LGD, x, 1.0f, cat, 2, 0);

        // ---------------- cross attention ----------------
        {
            dim3 grid(512 / 128, M4 / 64, 1);
            tgemm_k<64, 128, 1, 2><<<grid, 128, GSMEM64>>>(
                x, rcqkvW + (long)i * 512 * LGD, nullptr, M4, 512, LGD, 0,
                0, 0, 0, rcqkvB + (long)i * 512, nullptr, 1.0f, nullptr, 0,
                Q, nullptr, V, nullptr, nullptr);
        }
        flash_k<<<dim3(16, BH), 128, FSMEM>>>(Q, Q, V, ctx, 4);
        tgemm(ctx, rcOut + (long)i * LGD * LGD, cat + LGD, M4, LGD, LGD, 2 * LGD,
              0, 0, 0, 1, cOut_b + (long)i * LGD, nullptr, 1.0f, nullptr, 1, 0);
        tgemm(cat, rcF1 + (long)i * 4 * LGD * LGD, h1, M4, 2 * LGD, 2 * LGD, 2 * LGD,
              0, 0, 0, 1, cF1_b + (long)i * 2 * LGD, nullptr, 1.0f, nullptr, 0, 0);
        lngelu_k<<<M4, 256>>>(h1, cLN_g + (long)i * 2 * LGD, cLN_b + (long)i * 2 * LGD, h2);
        tgemm(h2, rcF2 + (long)i * 2 * LGD * LGD, x, M4, LGD, 2 * LGD, LGD,
              0, 0, 0, 1, cF2_b + (long)i * LGD, x, 1.0f, cat, 2, 0);
    }

    // ---------------- matching head ----------------
    tgemm(x, rfp, md, M4, LGD, LGD, LGD, 0, 0, 0, 1, fp_b, nullptr, 0.25f,
          nullptr, 1, 1);
    tgemm(md, md + (long)LGN * LGD, sim, LGN, LGN, LGD, LGN,
          (long)2 * LGN * LGD, (long)2 * LGN * LGD, sSS, 2, nullptr, nullptr, 1.0f,
          nullptr, 0, 0);
    z_k<<<M4, 256>>>(x, match_w, match_b, z);
    lse_row_k<<<2 * LGN, 256>>>(sim, lser);
    lse_col_k<<<64, 256>>>(sim, lsec);
    scores_k<<<(NN2 + 255) / 256, 256>>>(sim, lser, lsec, z, out);

    // ---------------- filter (batch 0 only) ----------------
    argmax_row_k<<<LGN, 256>>>(out, rmax, m0);
    argmax_col_k<<<32, 256>>>(out, m1);
    filter_k<<<1, 1024>>>(m0, m1, rmax, out);
}